// round 1
// baseline (speedup 1.0000x reference)
#include <cuda_runtime.h>
#include <math.h>

#define BATCH 8
#define DM    256
#define TLEN  2048
#define DIN   514
#define NL    4
#define NST   32

// ---------------- scratch (static __device__, allocation-free) ----------------
__device__ float g_zr [BATCH*DM*TLEN];
__device__ float g_zi [BATCH*DM*TLEN];
__device__ float g_ygr[BATCH*DM*TLEN];
__device__ float g_ygi[BATCH*DM*TLEN];
__device__ float g_or [BATCH*DM*TLEN];
__device__ float g_oi [BATCH*DM*TLEN];
__device__ float g_ar [NL*DM*NST];
__device__ float g_ai [NL*DM*NST];
__device__ float g_cr [NL*DM*NST];
__device__ float g_ci [NL*DM*NST];

__device__ __forceinline__ float gelu_tanh(float x) {
    // matches jax.nn.gelu(approximate=True)
    float x3 = x * x * x;
    float t  = 0.7978845608028654f * fmaf(0.044715f, x3, x);
    float th;
    asm("tanh.approx.f32 %0, %1;" : "=f"(th) : "f"(t));
    return 0.5f * x * (1.0f + th);
}

// ---------------- S4D coefficient precompute (exact recurrence params) --------
__global__ void precompute_kernel(const float* __restrict__ log_dt,
                                  const float* __restrict__ log_A_real,
                                  const float* __restrict__ A_imag,
                                  const float* __restrict__ C_r,
                                  const float* __restrict__ C_i)
{
    int idx = blockIdx.x * blockDim.x + threadIdx.x;
    if (idx >= NL*DM*NST) return;
    int h = (idx / NST) % DM;
    int l = idx / (NST*DM);
    double dt  = exp((double)log_dt[l*DM + h]);
    double Are = -exp((double)log_A_real[idx]);
    double Aim = (double)A_imag[idx];
    double dre = Are * dt, dim = Aim * dt;
    double er  = exp(dre);
    double arr = er * cos(dim);
    double aii = er * sin(dim);
    g_ar[idx] = (float)arr;
    g_ai[idx] = (float)aii;
    // (exp(dtA) - 1) / A
    double e1r = arr - 1.0, e1i = aii;
    double den = Are*Are + Aim*Aim;
    double qr  = (e1r*Are + e1i*Aim) / den;
    double qi  = (e1i*Are - e1r*Aim) / den;
    double cr  = (double)C_r[idx], ci = (double)C_i[idx];
    g_cr[idx] = (float)(cr*qr - ci*qi);
    g_ci[idx] = (float)(cr*qi + ci*qr);
}

// ---------------- encoder: complex GEMM (DIN=514 -> DM), x interleaved --------
__global__ __launch_bounds__(256) void encoder_gemm(const float* __restrict__ x,
    const float* __restrict__ Wr, const float* __restrict__ Wi,
    const float* __restrict__ br, const float* __restrict__ bi)
{
    __shared__ float2 Xs[16][64];
    __shared__ float2 Ws[16][64];
    int b  = blockIdx.z;
    int t0 = blockIdx.x * 64;
    int g0 = blockIdx.y * 64;
    int tid = threadIdx.x;
    int tx = tid & 15, ty = tid >> 4;
    float accR[4][4], accI[4][4];
#pragma unroll
    for (int i = 0; i < 4; i++)
#pragma unroll
        for (int j = 0; j < 4; j++) { accR[i][j] = 0.f; accI[i][j] = 0.f; }

    const float2* xc = reinterpret_cast<const float2*>(x);  // x[b][d][t] = (re,im)
    int lt  = tid & 63, lk4 = (tid >> 6) * 4;
    int lkw = tid & 15, lg  = tid >> 4;

    for (int k0 = 0; k0 < DIN; k0 += 16) {
#pragma unroll
        for (int p = 0; p < 4; p++) {
            int kk = lk4 + p;
            int k  = k0 + kk;
            float2 v = make_float2(0.f, 0.f);
            if (k < DIN) v = xc[((long)b*DIN + k)*TLEN + t0 + lt];
            Xs[kk][lt] = v;
        }
#pragma unroll
        for (int p = 0; p < 4; p++) {
            int gg = lg + p*16;
            int k  = k0 + lkw;
            float wr_ = 0.f, wi_ = 0.f;
            if (k < DIN) { wr_ = Wr[(g0+gg)*DIN + k]; wi_ = Wi[(g0+gg)*DIN + k]; }
            Ws[lkw][gg] = make_float2(wr_, wi_);
        }
        __syncthreads();
#pragma unroll
        for (int kk = 0; kk < 16; kk++) {
            float2 xv[4], wv[4];
#pragma unroll
            for (int i = 0; i < 4; i++) xv[i] = Xs[kk][tx + 16*i];
#pragma unroll
            for (int i = 0; i < 4; i++) wv[i] = Ws[kk][ty + 16*i];
#pragma unroll
            for (int gi = 0; gi < 4; gi++)
#pragma unroll
                for (int ti = 0; ti < 4; ti++) {
                    accR[gi][ti] = fmaf(wv[gi].x,  xv[ti].x, accR[gi][ti]);
                    accR[gi][ti] = fmaf(-wv[gi].y, xv[ti].y, accR[gi][ti]);
                    accI[gi][ti] = fmaf(wv[gi].x,  xv[ti].y, accI[gi][ti]);
                    accI[gi][ti] = fmaf(wv[gi].y,  xv[ti].x, accI[gi][ti]);
                }
        }
        __syncthreads();
    }
#pragma unroll
    for (int gi = 0; gi < 4; gi++) {
        int g = g0 + ty + 16*gi;
        float bR = br[g], bI = bi[g];
#pragma unroll
        for (int ti = 0; ti < 4; ti++) {
            int t = t0 + tx + 16*ti;
            long off = ((long)b*DM + g)*TLEN + t;
            g_zr[off] = accR[gi][ti] + bR;
            g_zi[off] = accI[gi][ti] + bI;
        }
    }
}

// ---------------- per-layer S4D scan + D-skip + gelu (warp = one (b,h)) ------
__global__ __launch_bounds__(128) void scan_kernel(int layer, const float* __restrict__ Dvec)
{
    __shared__ float2 uS[4][32];
    __shared__ float2 prodS[4][32][34];   // [t][n], padded rows
    int wid  = threadIdx.x >> 5;
    int lane = threadIdx.x & 31;
    int ch = blockIdx.x * 4 + wid;        // 0..2047
    int b  = ch >> 8;
    int h  = ch & 255;
    int pidx = (layer*DM + h)*NST + lane;
    float ar = g_ar[pidx], ai = g_ai[pidx];
    float cr = g_cr[pidx], ci = g_ci[pidx];
    float Dh = Dvec[layer*DM + h];
    long base = ((long)b*DM + h)*TLEN;
    const float* zr = g_zr + base;
    const float* zi = g_zi + base;
    float* yro = g_ygr + base;
    float* yio = g_ygi + base;

    float sr = 0.f, si = 0.f;
    for (int t0 = 0; t0 < TLEN; t0 += 32) {
        float ur_l = zr[t0 + lane];
        float ui_l = zi[t0 + lane];
        uS[wid][lane] = make_float2(ur_l, ui_l);
        __syncwarp();
#pragma unroll
        for (int j = 0; j < 32; j++) {
            float2 u = uS[wid][j];
            float nsr = fmaf(ar, sr, u.x); nsr = fmaf(-ai, si, nsr);
            float nsi = fmaf(ar, si, u.y); nsi = fmaf( ai, sr, nsi);
            sr = nsr; si = nsi;
            float pr = cr * sr; pr = fmaf(-ci, si, pr);
            float pi = cr * si; pi = fmaf( ci, sr, pi);
            prodS[wid][j][lane] = make_float2(pr, pi);
        }
        __syncwarp();
        float yr = 0.f, yi = 0.f;
#pragma unroll
        for (int q = 0; q < 32; q++) {
            float2 v = prodS[wid][lane][q];
            yr += v.x; yi += v.y;
        }
        yr = fmaf(Dh, ur_l, yr);
        yi = fmaf(Dh, ui_l, yi);
        yro[t0 + lane] = gelu_tanh(yr);
        yio[t0 + lane] = gelu_tanh(yi);
        __syncwarp();
    }
}

// ---------------- per-layer pointwise complex GEMM (DM -> DM) -----------------
__global__ __launch_bounds__(256) void outlin_gemm(int l,
    const float* __restrict__ Wr, const float* __restrict__ Wi,
    const float* __restrict__ br, const float* __restrict__ bi)
{
    __shared__ float2 Xs[16][64];
    __shared__ float2 Ws[16][64];
    int b  = blockIdx.z;
    int t0 = blockIdx.x * 64;
    int g0 = blockIdx.y * 64;
    int tid = threadIdx.x;
    int tx = tid & 15, ty = tid >> 4;
    float accR[4][4], accI[4][4];
#pragma unroll
    for (int i = 0; i < 4; i++)
#pragma unroll
        for (int j = 0; j < 4; j++) { accR[i][j] = 0.f; accI[i][j] = 0.f; }

    const float* wrp = Wr + (long)l*DM*DM;
    const float* wip = Wi + (long)l*DM*DM;
    int lt  = tid & 63, lk4 = (tid >> 6) * 4;
    int lkw = tid & 15, lg  = tid >> 4;

    for (int k0 = 0; k0 < DM; k0 += 16) {
#pragma unroll
        for (int p = 0; p < 4; p++) {
            int kk = lk4 + p;
            long off = ((long)b*DM + k0 + kk)*TLEN + t0 + lt;
            Xs[kk][lt] = make_float2(g_ygr[off], g_ygi[off]);
        }
#pragma unroll
        for (int p = 0; p < 4; p++) {
            int gg = lg + p*16;
            int k  = k0 + lkw;
            Ws[lkw][gg] = make_float2(wrp[(g0+gg)*DM + k], wip[(g0+gg)*DM + k]);
        }
        __syncthreads();
#pragma unroll
        for (int kk = 0; kk < 16; kk++) {
            float2 xv[4], wv[4];
#pragma unroll
            for (int i = 0; i < 4; i++) xv[i] = Xs[kk][tx + 16*i];
#pragma unroll
            for (int i = 0; i < 4; i++) wv[i] = Ws[kk][ty + 16*i];
#pragma unroll
            for (int gi = 0; gi < 4; gi++)
#pragma unroll
                for (int ti = 0; ti < 4; ti++) {
                    accR[gi][ti] = fmaf(wv[gi].x,  xv[ti].x, accR[gi][ti]);
                    accR[gi][ti] = fmaf(-wv[gi].y, xv[ti].y, accR[gi][ti]);
                    accI[gi][ti] = fmaf(wv[gi].x,  xv[ti].y, accI[gi][ti]);
                    accI[gi][ti] = fmaf(wv[gi].y,  xv[ti].x, accI[gi][ti]);
                }
        }
        __syncthreads();
    }
#pragma unroll
    for (int gi = 0; gi < 4; gi++) {
        int g = g0 + ty + 16*gi;
        float bR = br[l*DM + g], bI = bi[l*DM + g];
#pragma unroll
        for (int ti = 0; ti < 4; ti++) {
            int t = t0 + tx + 16*ti;
            long off = ((long)b*DM + g)*TLEN + t;
            g_or[off] = accR[gi][ti] + bR;
            g_oi[off] = accI[gi][ti] + bI;
        }
    }
}

// ---------------- residual + complex LayerNorm over channels ------------------
__global__ __launch_bounds__(256) void ln_kernel(int l,
    const float* __restrict__ gamma_r, const float* __restrict__ gamma_i,
    const float* __restrict__ beta_r,  const float* __restrict__ beta_i)
{
    int b  = blockIdx.y;
    int t0 = blockIdx.x * 32;
    int tt = threadIdx.x & 31;
    int gg = threadIdx.x >> 5;     // 0..7
    int t  = t0 + tt;

    float vr[32], vi[32];
    float sr = 0.f, qr = 0.f, si = 0.f, qi = 0.f;
#pragma unroll
    for (int j = 0; j < 32; j++) {
        int g = gg*32 + j;
        long off = ((long)b*DM + g)*TLEN + t;
        float r  = g_zr[off] + g_or[off];
        float i_ = g_zi[off] + g_oi[off];
        vr[j] = r; vi[j] = i_;
        sr += r;  qr = fmaf(r, r, qr);
        si += i_; qi = fmaf(i_, i_, qi);
    }
    __shared__ float red[4][8][32];
    red[0][gg][tt] = sr; red[1][gg][tt] = qr;
    red[2][gg][tt] = si; red[3][gg][tt] = qi;
    __syncthreads();
    float tsr = 0.f, tqr = 0.f, tsi = 0.f, tqi = 0.f;
#pragma unroll
    for (int k = 0; k < 8; k++) {
        tsr += red[0][k][tt]; tqr += red[1][k][tt];
        tsi += red[2][k][tt]; tqi += red[3][k][tt];
    }
    float mr  = tsr * (1.f/DM), mi_ = tsi * (1.f/DM);
    float var_r = tqr * (1.f/DM) - mr*mr;
    float var_i = tqi * (1.f/DM) - mi_*mi_;
    float rr = rsqrtf(var_r + 1e-5f);
    float ri = rsqrtf(var_i + 1e-5f);
#pragma unroll
    for (int j = 0; j < 32; j++) {
        int g = gg*32 + j;
        long off = ((long)b*DM + g)*TLEN + t;
        g_zr[off] = (vr[j] - mr)  * rr * gamma_r[l*DM + g] + beta_r[l*DM + g];
        g_zi[off] = (vi[j] - mi_) * ri * gamma_i[l*DM + g] + beta_i[l*DM + g];
    }
}

// ---------------- decoder: complex GEMM (DM -> DIN), interleaved output -------
__global__ __launch_bounds__(256) void decoder_gemm(
    const float* __restrict__ Wr, const float* __restrict__ Wi,
    const float* __restrict__ br, const float* __restrict__ bi,
    float2* __restrict__ out)
{
    __shared__ float2 Xs[16][64];
    __shared__ float2 Ws[16][64];
    int b  = blockIdx.z;
    int t0 = blockIdx.x * 64;
    int g0 = blockIdx.y * 64;   // output feature d
    int tid = threadIdx.x;
    int tx = tid & 15, ty = tid >> 4;
    float accR[4][4], accI[4][4];
#pragma unroll
    for (int i = 0; i < 4; i++)
#pragma unroll
        for (int j = 0; j < 4; j++) { accR[i][j] = 0.f; accI[i][j] = 0.f; }

    int lt  = tid & 63, lk4 = (tid >> 6) * 4;
    int lkw = tid & 15, lg  = tid >> 4;

    for (int k0 = 0; k0 < DM; k0 += 16) {
#pragma unroll
        for (int p = 0; p < 4; p++) {
            int kk = lk4 + p;
            long off = ((long)b*DM + k0 + kk)*TLEN + t0 + lt;
            Xs[kk][lt] = make_float2(g_zr[off], g_zi[off]);
        }
#pragma unroll
        for (int p = 0; p < 4; p++) {
            int gg = lg + p*16;
            int g  = g0 + gg;
            int k  = k0 + lkw;
            float wr_ = 0.f, wi_ = 0.f;
            if (g < DIN) { wr_ = Wr[(long)g*DM + k]; wi_ = Wi[(long)g*DM + k]; }
            Ws[lkw][gg] = make_float2(wr_, wi_);
        }
        __syncthreads();
#pragma unroll
        for (int kk = 0; kk < 16; kk++) {
            float2 xv[4], wv[4];
#pragma unroll
            for (int i = 0; i < 4; i++) xv[i] = Xs[kk][tx + 16*i];
#pragma unroll
            for (int i = 0; i < 4; i++) wv[i] = Ws[kk][ty + 16*i];
#pragma unroll
            for (int gi = 0; gi < 4; gi++)
#pragma unroll
                for (int ti = 0; ti < 4; ti++) {
                    accR[gi][ti] = fmaf(wv[gi].x,  xv[ti].x, accR[gi][ti]);
                    accR[gi][ti] = fmaf(-wv[gi].y, xv[ti].y, accR[gi][ti]);
                    accI[gi][ti] = fmaf(wv[gi].x,  xv[ti].y, accI[gi][ti]);
                    accI[gi][ti] = fmaf(wv[gi].y,  xv[ti].x, accI[gi][ti]);
                }
        }
        __syncthreads();
    }
#pragma unroll
    for (int gi = 0; gi < 4; gi++) {
        int g = g0 + ty + 16*gi;
        if (g >= DIN) continue;
        float bR = br[g], bI = bi[g];
#pragma unroll
        for (int ti = 0; ti < 4; ti++) {
            int t = t0 + tx + 16*ti;
            out[((long)b*DIN + g)*TLEN + t] = make_float2(accR[gi][ti] + bR,
                                                          accI[gi][ti] + bI);
        }
    }
}

// ---------------- launch ------------------------------------------------------
extern "C" void kernel_launch(void* const* d_in, const int* in_sizes, int n_in,
                              void* d_out, int out_size)
{
    const float* x          = (const float*)d_in[0];
    const float* enc_Wr     = (const float*)d_in[1];
    const float* enc_Wi     = (const float*)d_in[2];
    const float* enc_br     = (const float*)d_in[3];
    const float* enc_bi     = (const float*)d_in[4];
    const float* log_dt     = (const float*)d_in[5];
    const float* log_A_real = (const float*)d_in[6];
    const float* A_imag     = (const float*)d_in[7];
    const float* C_r        = (const float*)d_in[8];
    const float* C_i        = (const float*)d_in[9];
    const float* Dvec       = (const float*)d_in[10];
    const float* out_Wr     = (const float*)d_in[11];
    const float* out_Wi     = (const float*)d_in[12];
    const float* out_br     = (const float*)d_in[13];
    const float* out_bi     = (const float*)d_in[14];
    const float* ln_gamma_r = (const float*)d_in[15];
    const float* ln_gamma_i = (const float*)d_in[16];
    const float* ln_beta_r  = (const float*)d_in[17];
    const float* ln_beta_i  = (const float*)d_in[18];
    const float* dec_Wr     = (const float*)d_in[19];
    const float* dec_Wi     = (const float*)d_in[20];
    const float* dec_br     = (const float*)d_in[21];
    const float* dec_bi     = (const float*)d_in[22];

    precompute_kernel<<<(NL*DM*NST + 255)/256, 256>>>(log_dt, log_A_real, A_imag, C_r, C_i);

    encoder_gemm<<<dim3(TLEN/64, DM/64, BATCH), 256>>>(x, enc_Wr, enc_Wi, enc_br, enc_bi);

    for (int l = 0; l < NL; l++) {
        scan_kernel<<<(BATCH*DM)/4, 128>>>(l, Dvec);
        outlin_gemm<<<dim3(TLEN/64, DM/64, BATCH), 256>>>(l, out_Wr, out_Wi, out_br, out_bi);
        ln_kernel<<<dim3(TLEN/32, BATCH), 256>>>(l, ln_gamma_r, ln_gamma_i, ln_beta_r, ln_beta_i);
    }

    decoder_gemm<<<dim3(TLEN/64, (DIN + 63)/64, BATCH), 256>>>(dec_Wr, dec_Wi, dec_br, dec_bi,
                                                               (float2*)d_out);
}